// round 1
// baseline (speedup 1.0000x reference)
#include <cuda_runtime.h>

#define NHH 8
#define KD 32
#define HD 32
#define OC 1280     // NH*(4*KD+HD)
#define DIN 256
#define NPIX 4096   // 64*64
#define BB 2
#define OPH 160     // channels per head
#define SCALE 0.17677669529663687f

__device__ float g_p[BB * OC * NPIX];        // projection output
__device__ float g_R[BB * NHH * 64 * NPIX];  // row-attn weights R[bH][i][pix]
__device__ float g_C[BB * NHH * 64 * NPIX];  // col-attn weights C[bH][j][pix]

// ---------------- Kernel 1: projection GEMM  p[b,o,pix] = sum_c w[o,c] x[b,c,pix]
__global__ __launch_bounds__(256) void k_proj(const float* __restrict__ x,
                                              const float* __restrict__ w) {
    __shared__ float As[16][64];  // [k][m]
    __shared__ float Bs[16][64];  // [k][n]
    const int b  = blockIdx.z;
    const int m0 = blockIdx.y * 64;
    const int n0 = blockIdx.x * 64;
    const float* xb = x + (size_t)b * DIN * NPIX;
    const int t  = threadIdx.x;
    const int tm = t >> 4, tn = t & 15;
    const int lm = t >> 2, lk4 = (t & 3) * 4;   // A loader
    const int lk = t >> 4, ln4 = (t & 15) * 4;  // B loader
    float acc[4][4] = {};
    for (int k0 = 0; k0 < DIN; k0 += 16) {
        float4 a4 = *(const float4*)&w[(m0 + lm) * DIN + k0 + lk4];
        As[lk4 + 0][lm] = a4.x; As[lk4 + 1][lm] = a4.y;
        As[lk4 + 2][lm] = a4.z; As[lk4 + 3][lm] = a4.w;
        *(float4*)&Bs[lk][ln4] = *(const float4*)&xb[(k0 + lk) * NPIX + n0 + ln4];
        __syncthreads();
#pragma unroll
        for (int kk = 0; kk < 16; kk++) {
            float4 av = *(const float4*)&As[kk][tm * 4];
            float4 bv = *(const float4*)&Bs[kk][tn * 4];
            float a[4] = {av.x, av.y, av.z, av.w};
            float bvv[4] = {bv.x, bv.y, bv.z, bv.w};
#pragma unroll
            for (int ii = 0; ii < 4; ii++)
#pragma unroll
                for (int jj = 0; jj < 4; jj++)
                    acc[ii][jj] = fmaf(a[ii], bvv[jj], acc[ii][jj]);
        }
        __syncthreads();
    }
    float* pp = g_p + (size_t)b * OC * NPIX;
#pragma unroll
    for (int ii = 0; ii < 4; ii++) {
        float4 o = {acc[ii][0], acc[ii][1], acc[ii][2], acc[ii][3]};
        *(float4*)&pp[(m0 + tm * 4 + ii) * NPIX + n0 + tn * 4] = o;
    }
}

// ---------------- Kernel 2: row attention.  Block per (b,H,w).
// A[i,j] = SCALE * sum_d rq[d,i]*rk[d,j]; softmax over i; R[i, j*64+w] = result.
__global__ __launch_bounds__(256) void k_rowattn() {
    __shared__ float sq[32][64];
    __shared__ float sk[32][64];
    __shared__ float A[64][65];
    const int w = blockIdx.x, H = blockIdx.y, b = blockIdx.z;
    const int t = threadIdx.x;
    const float* pq = g_p + ((size_t)(b * OC) + H * OPH) * NPIX;
    const float* pk = pq + (size_t)KD * NPIX;
    for (int idx = t; idx < 32 * 64; idx += 256) {
        int d = idx >> 6, i = idx & 63;
        sq[d][i] = pq[(size_t)d * NPIX + i * 64 + w];
        sk[d][i] = pk[(size_t)d * NPIX + i * 64 + w];
    }
    __syncthreads();
    {
        const int ti = (t >> 4) * 4, tj = (t & 15) * 4;
        float acc[4][4] = {};
#pragma unroll 8
        for (int d = 0; d < 32; d++) {
            float4 av = *(const float4*)&sq[d][ti];
            float4 bv = *(const float4*)&sk[d][tj];
            float a[4] = {av.x, av.y, av.z, av.w};
            float bb2[4] = {bv.x, bv.y, bv.z, bv.w};
#pragma unroll
            for (int ii = 0; ii < 4; ii++)
#pragma unroll
                for (int jj = 0; jj < 4; jj++)
                    acc[ii][jj] = fmaf(a[ii], bb2[jj], acc[ii][jj]);
        }
#pragma unroll
        for (int ii = 0; ii < 4; ii++)
#pragma unroll
            for (int jj = 0; jj < 4; jj++)
                A[ti + ii][tj + jj] = acc[ii][jj] * SCALE;
    }
    __syncthreads();
    const int wid = t >> 5, lane = t & 31;
    float* Rb = g_R + (size_t)(b * NHH + H) * 64 * NPIX;
#pragma unroll
    for (int jj = 0; jj < 8; jj++) {
        int j = wid * 8 + jj;
        float v0 = A[lane][j], v1 = A[lane + 32][j];
        float m = fmaxf(v0, v1);
#pragma unroll
        for (int s = 16; s; s >>= 1) m = fmaxf(m, __shfl_xor_sync(0xffffffffu, m, s));
        float e0 = __expf(v0 - m), e1 = __expf(v1 - m);
        float sm = e0 + e1;
#pragma unroll
        for (int s = 16; s; s >>= 1) sm += __shfl_xor_sync(0xffffffffu, sm, s);
        float inv = 1.0f / sm;
        Rb[(size_t)lane * NPIX + j * 64 + w] = e0 * inv;
        Rb[(size_t)(lane + 32) * NPIX + j * 64 + w] = e1 * inv;
    }
}

// ---------------- Kernel 3: column attention.  Block per (b,H,h).
// A[jj,w] = SCALE * sum_d cq[d,jj]*ck[d,w]; softmax over jj; C[jj, h*64+w].
__global__ __launch_bounds__(256) void k_colattn() {
    __shared__ float sq[32][64];
    __shared__ float sk[32][64];
    __shared__ float A[64][65];
    const int h = blockIdx.x, H = blockIdx.y, b = blockIdx.z;
    const int t = threadIdx.x;
    const float* pq = g_p + ((size_t)(b * OC) + H * OPH + 2 * KD) * NPIX + h * 64;
    const float* pk = g_p + ((size_t)(b * OC) + H * OPH + 3 * KD) * NPIX + h * 64;
#pragma unroll
    for (int u = 0; u < 2; u++) {
        int e = t + u * 256;           // 0..511 -> 512 float4 loads per array
        int d = e >> 4, c4 = (e & 15) * 4;
        *(float4*)&sq[d][c4] = *(const float4*)&pq[(size_t)d * NPIX + c4];
        *(float4*)&sk[d][c4] = *(const float4*)&pk[(size_t)d * NPIX + c4];
    }
    __syncthreads();
    {
        const int ti = (t >> 4) * 4, tj = (t & 15) * 4;
        float acc[4][4] = {};
#pragma unroll 8
        for (int d = 0; d < 32; d++) {
            float4 av = *(const float4*)&sq[d][ti];
            float4 bv = *(const float4*)&sk[d][tj];
            float a[4] = {av.x, av.y, av.z, av.w};
            float bb2[4] = {bv.x, bv.y, bv.z, bv.w};
#pragma unroll
            for (int ii = 0; ii < 4; ii++)
#pragma unroll
                for (int jj = 0; jj < 4; jj++)
                    acc[ii][jj] = fmaf(a[ii], bb2[jj], acc[ii][jj]);
        }
#pragma unroll
        for (int ii = 0; ii < 4; ii++)
#pragma unroll
            for (int jj = 0; jj < 4; jj++)
                A[ti + ii][tj + jj] = acc[ii][jj] * SCALE;
    }
    __syncthreads();
    const int wid = t >> 5, lane = t & 31;
#pragma unroll
    for (int jj = 0; jj < 8; jj++) {
        int j = wid * 8 + jj;   // the w column
        float v0 = A[lane][j], v1 = A[lane + 32][j];
        float m = fmaxf(v0, v1);
#pragma unroll
        for (int s = 16; s; s >>= 1) m = fmaxf(m, __shfl_xor_sync(0xffffffffu, m, s));
        float e0 = __expf(v0 - m), e1 = __expf(v1 - m);
        float sm = e0 + e1;
#pragma unroll
        for (int s = 16; s; s >>= 1) sm += __shfl_xor_sync(0xffffffffu, sm, s);
        float inv = 1.0f / sm;
        A[lane][j] = e0 * inv;
        A[lane + 32][j] = e1 * inv;
    }
    __syncthreads();
    float* Cb = g_C + (size_t)(b * NHH + H) * 64 * NPIX + h * 64;
    for (int idx = t; idx < 64 * 64; idx += 256) {
        int jj = idx >> 6, ww = idx & 63;
        Cb[(size_t)jj * NPIX + ww] = A[jj][ww];   // coalesced in ww
    }
}

// ---------------- Kernel 4: out[d,p] = sum_{i,j} V[d,i*64+j]*R[i,p]*C[j,p] + V[d,p]
// Block per (b,H,pixel-tile of 128). G[j,p]=R[i,p]*C[j,p] built in SMEM per i-slab.
__global__ __launch_bounds__(256) void k_final(float* __restrict__ out) {
    extern __shared__ float smf[];
    float* Rt  = smf;                  // [64][128]
    float* Ct  = smf + 64 * 128;       // [64][128]
    float* Gs  = smf + 2 * 64 * 128;   // [64][128]
    float* Vst = smf + 3 * 64 * 128;   // [64][32]  (j-major, d contiguous)
    const int p0 = blockIdx.x * 128;
    const int H = blockIdx.y, b = blockIdx.z;
    const int t = threadIdx.x;
    const int bH = b * NHH + H;
    const float* Rg = g_R + (size_t)bH * 64 * NPIX + p0;
    const float* Cg = g_C + (size_t)bH * 64 * NPIX + p0;
    const float* Vg = g_p + ((size_t)(b * OC) + H * OPH + 4 * KD) * NPIX;
#pragma unroll
    for (int u = 0; u < 8; u++) {
        int e = t + u * 256;           // 2048 float4 per array
        int r = e >> 5, c4 = (e & 31) * 4;
        *(float4*)&Rt[r * 128 + c4] = *(const float4*)&Rg[(size_t)r * NPIX + c4];
        *(float4*)&Ct[r * 128 + c4] = *(const float4*)&Cg[(size_t)r * NPIX + c4];
    }
    __syncthreads();
    const int tm = t >> 5;   // warp id -> d base = tm*4 (broadcast-friendly)
    const int tn = t & 31;   // p base = tn*4
    float acc[4][4] = {};
    for (int i = 0; i < 64; i++) {
        // V slab, transposed: Vst[j][d] = V[d, i*64+j]
#pragma unroll
        for (int u = 0; u < 2; u++) {
            int e = t + u * 256;       // 512 float4
            int d = e & 31, j = (e >> 5) * 4;
            float4 v4 = *(const float4*)&Vg[(size_t)d * NPIX + i * 64 + j];
            Vst[(j + 0) * 32 + d] = v4.x; Vst[(j + 1) * 32 + d] = v4.y;
            Vst[(j + 2) * 32 + d] = v4.z; Vst[(j + 3) * 32 + d] = v4.w;
        }
        // Gs[j][p] = Rt[i][p] * Ct[j][p]
#pragma unroll
        for (int u = 0; u < 8; u++) {
            int e = t + u * 256;
            int j = e >> 5, c4 = (e & 31) * 4;
            float4 r4 = *(const float4*)&Rt[i * 128 + c4];
            float4 cv = *(const float4*)&Ct[j * 128 + c4];
            float4 g;
            g.x = r4.x * cv.x; g.y = r4.y * cv.y;
            g.z = r4.z * cv.z; g.w = r4.w * cv.w;
            *(float4*)&Gs[j * 128 + c4] = g;
        }
        __syncthreads();
#pragma unroll 8
        for (int j = 0; j < 64; j++) {
            float4 v = *(const float4*)&Vst[j * 32 + tm * 4];  // warp broadcast
            float4 g = *(const float4*)&Gs[j * 128 + tn * 4];
            float vv[4] = {v.x, v.y, v.z, v.w};
            float gg[4] = {g.x, g.y, g.z, g.w};
#pragma unroll
            for (int ii = 0; ii < 4; ii++)
#pragma unroll
                for (int jj = 0; jj < 4; jj++)
                    acc[ii][jj] = fmaf(vv[ii], gg[jj], acc[ii][jj]);
        }
        __syncthreads();
    }
#pragma unroll
    for (int ii = 0; ii < 4; ii++) {
        int d = tm * 4 + ii;
        float4 r = *(const float4*)&Vg[(size_t)d * NPIX + p0 + tn * 4];
        float4 o = {acc[ii][0] + r.x, acc[ii][1] + r.y,
                    acc[ii][2] + r.z, acc[ii][3] + r.w};
        *(float4*)&out[((size_t)(b * 256) + H * 32 + d) * NPIX + p0 + tn * 4] = o;
    }
}

extern "C" void kernel_launch(void* const* d_in, const int* in_sizes, int n_in,
                              void* d_out, int out_size) {
    const float* x = (const float*)d_in[0];
    const float* w = (const float*)d_in[1];
    if (n_in >= 2 && in_sizes[0] == OC * DIN) {  // defensive: swap if order differs
        const float* tmp = x; x = w; w = tmp;
    }
    float* out = (float*)d_out;
    const int FINAL_SMEM = (3 * 64 * 128 + 64 * 32) * (int)sizeof(float);  // 104 KB
    cudaFuncSetAttribute(k_final, cudaFuncAttributeMaxDynamicSharedMemorySize, FINAL_SMEM);

    k_proj<<<dim3(64, 20, BB), 256>>>(x, w);
    k_rowattn<<<dim3(64, NHH, BB), 256>>>();
    k_colattn<<<dim3(64, NHH, BB), 256>>>();
    k_final<<<dim3(32, NHH, BB), 256, FINAL_SMEM>>>(out);
}

// round 2
// speedup vs baseline: 1.1416x; 1.1416x over previous
#include <cuda_runtime.h>

#define NHH 8
#define KD 32
#define HD 32
#define OC 1280     // NH*(4*KD+HD)
#define DIN 256
#define NPIX 4096   // 64*64
#define BB 2
#define OPH 160     // channels per head
#define SCALE 0.17677669529663687f

typedef unsigned long long u64;

__device__ float g_p[BB * OC * NPIX];        // projection output
__device__ float g_R[BB * NHH * 64 * NPIX];  // row-attn weights R[bH][i][pix]
__device__ float g_C[BB * NHH * 64 * NPIX];  // col-attn weights C[bH][j][pix]

// ---- packed f32x2 helpers (sm_103a FFMA2: 2 fp32 FMA per issue slot) ----
__device__ __forceinline__ u64 ffma2(u64 a, u64 b, u64 c) {
    u64 d;
    asm("fma.rn.f32x2 %0, %1, %2, %3;" : "=l"(d) : "l"(a), "l"(b), "l"(c));
    return d;
}
__device__ __forceinline__ u64 fmul2(u64 a, u64 b) {
    u64 d;
    asm("mul.rn.f32x2 %0, %1, %2;" : "=l"(d) : "l"(a), "l"(b));
    return d;
}
__device__ __forceinline__ u64 fdup(float v) {
    u64 d;
    asm("mov.b64 %0, {%1, %1};" : "=l"(d) : "f"(v));
    return d;
}
__device__ __forceinline__ float lo32(u64 v) { return __uint_as_float((unsigned)v); }
__device__ __forceinline__ float hi32(u64 v) { return __uint_as_float((unsigned)(v >> 32)); }

// ---------------- Kernel 1: projection GEMM  p[b,o,pix] = sum_c w[o,c] x[b,c,pix]
// 64x64 tile, 256 threads, thread = 4m x 4n with packed-n FFMA2.
__global__ __launch_bounds__(256) void k_proj(const float* __restrict__ x,
                                              const float* __restrict__ w) {
    __shared__ float As[16][64];  // [k][m]
    __shared__ float Bs[16][64];  // [k][n]
    const int b  = blockIdx.z;
    const int m0 = blockIdx.y * 64;
    const int n0 = blockIdx.x * 64;
    const float* xb = x + (size_t)b * DIN * NPIX;
    const int t  = threadIdx.x;
    const int tm = t >> 4, tn = t & 15;
    const int lm = t >> 2, lk4 = (t & 3) * 4;   // A loader
    const int lk = t >> 4, ln4 = (t & 15) * 4;  // B loader
    u64 acc[4][2] = {};
    for (int k0 = 0; k0 < DIN; k0 += 16) {
        float4 a4 = *(const float4*)&w[(m0 + lm) * DIN + k0 + lk4];
        As[lk4 + 0][lm] = a4.x; As[lk4 + 1][lm] = a4.y;
        As[lk4 + 2][lm] = a4.z; As[lk4 + 3][lm] = a4.w;
        *(float4*)&Bs[lk][ln4] = *(const float4*)&xb[(k0 + lk) * NPIX + n0 + ln4];
        __syncthreads();
#pragma unroll
        for (int kk = 0; kk < 16; kk++) {
            float4 av = *(const float4*)&As[kk][tm * 4];
            ulonglong2 bv = *(const ulonglong2*)&Bs[kk][tn * 4];
            u64 a2[4] = {fdup(av.x), fdup(av.y), fdup(av.z), fdup(av.w)};
#pragma unroll
            for (int ii = 0; ii < 4; ii++) {
                acc[ii][0] = ffma2(a2[ii], bv.x, acc[ii][0]);
                acc[ii][1] = ffma2(a2[ii], bv.y, acc[ii][1]);
            }
        }
        __syncthreads();
    }
    float* pp = g_p + (size_t)b * OC * NPIX;
#pragma unroll
    for (int ii = 0; ii < 4; ii++) {
        float4 o = {lo32(acc[ii][0]), hi32(acc[ii][0]),
                    lo32(acc[ii][1]), hi32(acc[ii][1])};
        *(float4*)&pp[(m0 + tm * 4 + ii) * NPIX + n0 + tn * 4] = o;
    }
}

// ---------------- Kernel 2: row attention.  Block per (b,H,w).
__global__ __launch_bounds__(256) void k_rowattn() {
    __shared__ float sq[32][64];
    __shared__ float sk[32][64];
    __shared__ float A[64][65];
    const int w = blockIdx.x, H = blockIdx.y, b = blockIdx.z;
    const int t = threadIdx.x;
    const float* pq = g_p + ((size_t)(b * OC) + H * OPH) * NPIX;
    const float* pk = pq + (size_t)KD * NPIX;
    for (int idx = t; idx < 32 * 64; idx += 256) {
        int d = idx >> 6, i = idx & 63;
        sq[d][i] = pq[(size_t)d * NPIX + i * 64 + w];
        sk[d][i] = pk[(size_t)d * NPIX + i * 64 + w];
    }
    __syncthreads();
    {
        const int ti = (t >> 4) * 4, tj = (t & 15) * 4;
        float acc[4][4] = {};
#pragma unroll 8
        for (int d = 0; d < 32; d++) {
            float4 av = *(const float4*)&sq[d][ti];
            float4 bv = *(const float4*)&sk[d][tj];
            float a[4] = {av.x, av.y, av.z, av.w};
            float bb2[4] = {bv.x, bv.y, bv.z, bv.w};
#pragma unroll
            for (int ii = 0; ii < 4; ii++)
#pragma unroll
                for (int jj = 0; jj < 4; jj++)
                    acc[ii][jj] = fmaf(a[ii], bb2[jj], acc[ii][jj]);
        }
#pragma unroll
        for (int ii = 0; ii < 4; ii++)
#pragma unroll
            for (int jj = 0; jj < 4; jj++)
                A[ti + ii][tj + jj] = acc[ii][jj] * SCALE;
    }
    __syncthreads();
    const int wid = t >> 5, lane = t & 31;
    float* Rb = g_R + (size_t)(b * NHH + H) * 64 * NPIX;
#pragma unroll
    for (int jj = 0; jj < 8; jj++) {
        int j = wid * 8 + jj;
        float v0 = A[lane][j], v1 = A[lane + 32][j];
        float m = fmaxf(v0, v1);
#pragma unroll
        for (int s = 16; s; s >>= 1) m = fmaxf(m, __shfl_xor_sync(0xffffffffu, m, s));
        float e0 = __expf(v0 - m), e1 = __expf(v1 - m);
        float sm = e0 + e1;
#pragma unroll
        for (int s = 16; s; s >>= 1) sm += __shfl_xor_sync(0xffffffffu, sm, s);
        float inv = 1.0f / sm;
        Rb[(size_t)lane * NPIX + j * 64 + w] = e0 * inv;
        Rb[(size_t)(lane + 32) * NPIX + j * 64 + w] = e1 * inv;
    }
}

// ---------------- Kernel 3: column attention.  Block per (b,H,h).
__global__ __launch_bounds__(256) void k_colattn() {
    __shared__ float sq[32][64];
    __shared__ float sk[32][64];
    __shared__ float A[64][65];
    const int h = blockIdx.x, H = blockIdx.y, b = blockIdx.z;
    const int t = threadIdx.x;
    const float* pq = g_p + ((size_t)(b * OC) + H * OPH + 2 * KD) * NPIX + h * 64;
    const float* pk = g_p + ((size_t)(b * OC) + H * OPH + 3 * KD) * NPIX + h * 64;
#pragma unroll
    for (int u = 0; u < 2; u++) {
        int e = t + u * 256;
        int d = e >> 4, c4 = (e & 15) * 4;
        *(float4*)&sq[d][c4] = *(const float4*)&pq[(size_t)d * NPIX + c4];
        *(float4*)&sk[d][c4] = *(const float4*)&pk[(size_t)d * NPIX + c4];
    }
    __syncthreads();
    {
        const int ti = (t >> 4) * 4, tj = (t & 15) * 4;
        float acc[4][4] = {};
#pragma unroll 8
        for (int d = 0; d < 32; d++) {
            float4 av = *(const float4*)&sq[d][ti];
            float4 bv = *(const float4*)&sk[d][tj];
            float a[4] = {av.x, av.y, av.z, av.w};
            float bb2[4] = {bv.x, bv.y, bv.z, bv.w};
#pragma unroll
            for (int ii = 0; ii < 4; ii++)
#pragma unroll
                for (int jj = 0; jj < 4; jj++)
                    acc[ii][jj] = fmaf(a[ii], bb2[jj], acc[ii][jj]);
        }
#pragma unroll
        for (int ii = 0; ii < 4; ii++)
#pragma unroll
            for (int jj = 0; jj < 4; jj++)
                A[ti + ii][tj + jj] = acc[ii][jj] * SCALE;
    }
    __syncthreads();
    const int wid = t >> 5, lane = t & 31;
#pragma unroll
    for (int jj = 0; jj < 8; jj++) {
        int j = wid * 8 + jj;
        float v0 = A[lane][j], v1 = A[lane + 32][j];
        float m = fmaxf(v0, v1);
#pragma unroll
        for (int s = 16; s; s >>= 1) m = fmaxf(m, __shfl_xor_sync(0xffffffffu, m, s));
        float e0 = __expf(v0 - m), e1 = __expf(v1 - m);
        float sm = e0 + e1;
#pragma unroll
        for (int s = 16; s; s >>= 1) sm += __shfl_xor_sync(0xffffffffu, sm, s);
        float inv = 1.0f / sm;
        A[lane][j] = e0 * inv;
        A[lane + 32][j] = e1 * inv;
    }
    __syncthreads();
    float* Cb = g_C + (size_t)(b * NHH + H) * 64 * NPIX + h * 64;
    for (int idx = t; idx < 64 * 64; idx += 256) {
        int jj = idx >> 6, ww = idx & 63;
        Cb[(size_t)jj * NPIX + ww] = A[jj][ww];
    }
}

// ---------------- Kernel 4: out[d,p] = sum_{i,j} V[d,ij]*R[i,p]*C[j,p] + V[d,p]
// 128 threads, block tile 32d x 128p, thread tile 8d x 4p (packed-p FFMA2).
// C resident in SMEM; R streamed from global per i (4x L1 reuse);
// g = r*c computed in registers (no Gs materialization).
__global__ __launch_bounds__(128) void k_final(float* __restrict__ out) {
    __shared__ float Ct[64][128];   // 32 KB
    __shared__ float Vst[64][36];   // 9.2 KB, padded rows
    const int p0 = blockIdx.x * 128;
    const int H = blockIdx.y, b = blockIdx.z;
    const int t = threadIdx.x;
    const int td = t >> 5, tn = t & 31;
    const int d0 = td * 8, p4 = tn * 4;
    const int bH = b * NHH + H;
    const float* Rg = g_R + (size_t)bH * 64 * NPIX + p0;
    const float* Cg = g_C + (size_t)bH * 64 * NPIX + p0;
    const float* Vg = g_p + ((size_t)(b * OC) + H * OPH + 4 * KD) * NPIX;

    // Load C tile: 64 rows x 128 cols = 2048 float4
#pragma unroll
    for (int u = 0; u < 16; u++) {
        int e = t + u * 128;
        int r = e >> 5, c4 = (e & 31) * 4;
        *(float4*)&Ct[r][c4] = *(const float4*)&Cg[(size_t)r * NPIX + c4];
    }

    u64 acc[8][2] = {};
    for (int i = 0; i < 64; i++) {
        // R row for this i: 4 pixels per thread, packed pairs
        ulonglong2 rr = *(const ulonglong2*)&Rg[(size_t)i * NPIX + p4];
        // Build V slab transposed: Vst[j][d] = V[d, i*64+j] (coalesced loads)
#pragma unroll
        for (int u = 0; u < 4; u++) {
            int e = t + u * 128;             // 512 float4 units
            int d = e >> 4, j4 = (e & 15) * 4;
            float4 v4 = *(const float4*)&Vg[(size_t)d * NPIX + i * 64 + j4];
            Vst[j4 + 0][d] = v4.x; Vst[j4 + 1][d] = v4.y;
            Vst[j4 + 2][d] = v4.z; Vst[j4 + 3][d] = v4.w;
        }
        __syncthreads();
#pragma unroll 2
        for (int j = 0; j < 64; j++) {
            ulonglong2 cc = *(const ulonglong2*)&Ct[j][p4];
            u64 g0 = fmul2(rr.x, cc.x);
            u64 g1 = fmul2(rr.y, cc.y);
            float4 va = *(const float4*)&Vst[j][d0];       // warp-broadcast
            float4 vb = *(const float4*)&Vst[j][d0 + 4];   // warp-broadcast
            u64 v2[8] = {fdup(va.x), fdup(va.y), fdup(va.z), fdup(va.w),
                         fdup(vb.x), fdup(vb.y), fdup(vb.z), fdup(vb.w)};
#pragma unroll
            for (int k = 0; k < 8; k++) {
                acc[k][0] = ffma2(v2[k], g0, acc[k][0]);
                acc[k][1] = ffma2(v2[k], g1, acc[k][1]);
            }
        }
        __syncthreads();
    }
    // Epilogue: add residual V and store
#pragma unroll
    for (int k = 0; k < 8; k++) {
        int d = d0 + k;
        float4 r = *(const float4*)&Vg[(size_t)d * NPIX + p0 + p4];
        float4 o = {lo32(acc[k][0]) + r.x, hi32(acc[k][0]) + r.y,
                    lo32(acc[k][1]) + r.z, hi32(acc[k][1]) + r.w};
        *(float4*)&out[((size_t)(b * 256) + H * 32 + d) * NPIX + p0 + p4] = o;
    }
}

extern "C" void kernel_launch(void* const* d_in, const int* in_sizes, int n_in,
                              void* d_out, int out_size) {
    const float* x = (const float*)d_in[0];
    const float* w = (const float*)d_in[1];
    if (n_in >= 2 && in_sizes[0] == OC * DIN) {  // defensive: swap if order differs
        const float* tmp = x; x = w; w = tmp;
    }
    float* out = (float*)d_out;

    k_proj<<<dim3(64, 20, BB), 256>>>(x, w);
    k_rowattn<<<dim3(64, NHH, BB), 256>>>();
    k_colattn<<<dim3(64, NHH, BB), 256>>>();
    k_final<<<dim3(32, NHH, BB), 128>>>(out);
}

// round 6
// speedup vs baseline: 2.7289x; 2.3905x over previous
#include <cuda_runtime.h>
#include <cuda_fp16.h>

#define NHH 8
#define KD 32
#define HD 32
#define OC 1280     // NH*(4*KD+HD)
#define DIN 256
#define NPIX 4096   // 64*64
#define BB 2
#define OPH 160     // channels per head
#define SCALE 0.17677669529663687f

typedef unsigned long long u64;
typedef unsigned int u32;

__device__ float g_p[BB * OC * NPIX];        // projection output
__device__ float g_R[BB * NHH * 64 * NPIX];  // row-attn weights R[bH][i][pix]
__device__ float g_C[BB * NHH * 64 * NPIX];  // col-attn weights C[bH][j][pix]

// ---- packed f32x2 helpers ----
__device__ __forceinline__ u64 ffma2(u64 a, u64 b, u64 c) {
    u64 d;
    asm("fma.rn.f32x2 %0, %1, %2, %3;" : "=l"(d) : "l"(a), "l"(b), "l"(c));
    return d;
}
__device__ __forceinline__ u64 fdup(float v) {
    u64 d;
    asm("mov.b64 %0, {%1, %1};" : "=l"(d) : "f"(v));
    return d;
}
__device__ __forceinline__ float lo32(u64 v) { return __uint_as_float((unsigned)v); }
__device__ __forceinline__ float hi32(u64 v) { return __uint_as_float((unsigned)(v >> 32)); }

__device__ __forceinline__ u32 smem_u32(const void* p) {
    u32 a;
    asm("{ .reg .u64 t; cvta.to.shared.u64 t, %1; cvt.u32.u64 %0, t; }" : "=r"(a) : "l"(p));
    return a;
}
__device__ __forceinline__ u32 h2u(__half2 h) { return *(u32*)&h; }

// ---------------- Kernel 1: projection GEMM  p[b,o,pix] = sum_c w[o,c] x[b,c,pix]
__global__ __launch_bounds__(256) void k_proj(const float* __restrict__ x,
                                              const float* __restrict__ w) {
    __shared__ float As[16][64];  // [k][m]
    __shared__ float Bs[16][64];  // [k][n]
    const int b  = blockIdx.z;
    const int m0 = blockIdx.y * 64;
    const int n0 = blockIdx.x * 64;
    const float* xb = x + (size_t)b * DIN * NPIX;
    const int t  = threadIdx.x;
    const int tm = t >> 4, tn = t & 15;
    const int lm = t >> 2, lk4 = (t & 3) * 4;
    const int lk = t >> 4, ln4 = (t & 15) * 4;
    u64 acc[4][2] = {};
    for (int k0 = 0; k0 < DIN; k0 += 16) {
        float4 a4 = *(const float4*)&w[(m0 + lm) * DIN + k0 + lk4];
        As[lk4 + 0][lm] = a4.x; As[lk4 + 1][lm] = a4.y;
        As[lk4 + 2][lm] = a4.z; As[lk4 + 3][lm] = a4.w;
        *(float4*)&Bs[lk][ln4] = *(const float4*)&xb[(k0 + lk) * NPIX + n0 + ln4];
        __syncthreads();
#pragma unroll
        for (int kk = 0; kk < 16; kk++) {
            float4 av = *(const float4*)&As[kk][tm * 4];
            ulonglong2 bv = *(const ulonglong2*)&Bs[kk][tn * 4];
            u64 a2[4] = {fdup(av.x), fdup(av.y), fdup(av.z), fdup(av.w)};
#pragma unroll
            for (int ii = 0; ii < 4; ii++) {
                acc[ii][0] = ffma2(a2[ii], bv.x, acc[ii][0]);
                acc[ii][1] = ffma2(a2[ii], bv.y, acc[ii][1]);
            }
        }
        __syncthreads();
    }
    float* pp = g_p + (size_t)b * OC * NPIX;
#pragma unroll
    for (int ii = 0; ii < 4; ii++) {
        float4 o = {lo32(acc[ii][0]), hi32(acc[ii][0]),
                    lo32(acc[ii][1]), hi32(acc[ii][1])};
        *(float4*)&pp[(m0 + tm * 4 + ii) * NPIX + n0 + tn * 4] = o;
    }
}

// ---------------- Kernel 2: row attention.  Block per (b,H,w).
__global__ __launch_bounds__(256) void k_rowattn() {
    __shared__ float sq[32][64];
    __shared__ float sk[32][64];
    __shared__ float A[64][65];
    const int w = blockIdx.x, H = blockIdx.y, b = blockIdx.z;
    const int t = threadIdx.x;
    const float* pq = g_p + ((size_t)(b * OC) + H * OPH) * NPIX;
    const float* pk = pq + (size_t)KD * NPIX;
    for (int idx = t; idx < 32 * 64; idx += 256) {
        int d = idx >> 6, i = idx & 63;
        sq[d][i] = pq[(size_t)d * NPIX + i * 64 + w];
        sk[d][i] = pk[(size_t)d * NPIX + i * 64 + w];
    }
    __syncthreads();
    {
        const int ti = (t >> 4) * 4, tj = (t & 15) * 4;
        float acc[4][4] = {};
#pragma unroll 8
        for (int d = 0; d < 32; d++) {
            float4 av = *(const float4*)&sq[d][ti];
            float4 bv = *(const float4*)&sk[d][tj];
            float a[4] = {av.x, av.y, av.z, av.w};
            float bb2[4] = {bv.x, bv.y, bv.z, bv.w};
#pragma unroll
            for (int ii = 0; ii < 4; ii++)
#pragma unroll
                for (int jj = 0; jj < 4; jj++)
                    acc[ii][jj] = fmaf(a[ii], bb2[jj], acc[ii][jj]);
        }
#pragma unroll
        for (int ii = 0; ii < 4; ii++)
#pragma unroll
            for (int jj = 0; jj < 4; jj++)
                A[ti + ii][tj + jj] = acc[ii][jj] * SCALE;
    }
    __syncthreads();
    const int wid = t >> 5, lane = t & 31;
    float* Rb = g_R + (size_t)(b * NHH + H) * 64 * NPIX;
#pragma unroll
    for (int jj = 0; jj < 8; jj++) {
        int j = wid * 8 + jj;
        float v0 = A[lane][j], v1 = A[lane + 32][j];
        float m = fmaxf(v0, v1);
#pragma unroll
        for (int s = 16; s; s >>= 1) m = fmaxf(m, __shfl_xor_sync(0xffffffffu, m, s));
        float e0 = __expf(v0 - m), e1 = __expf(v1 - m);
        float sm = e0 + e1;
#pragma unroll
        for (int s = 16; s; s >>= 1) sm += __shfl_xor_sync(0xffffffffu, sm, s);
        float inv = 1.0f / sm;
        Rb[(size_t)lane * NPIX + j * 64 + w] = e0 * inv;
        Rb[(size_t)(lane + 32) * NPIX + j * 64 + w] = e1 * inv;
    }
}

// ---------------- Kernel 3: column attention.  Block per (b,H,h).
__global__ __launch_bounds__(256) void k_colattn() {
    __shared__ float sq[32][64];
    __shared__ float sk[32][64];
    __shared__ float A[64][65];
    const int h = blockIdx.x, H = blockIdx.y, b = blockIdx.z;
    const int t = threadIdx.x;
    const float* pq = g_p + ((size_t)(b * OC) + H * OPH + 2 * KD) * NPIX + h * 64;
    const float* pk = g_p + ((size_t)(b * OC) + H * OPH + 3 * KD) * NPIX + h * 64;
#pragma unroll
    for (int u = 0; u < 2; u++) {
        int e = t + u * 256;
        int d = e >> 4, c4 = (e & 15) * 4;
        *(float4*)&sq[d][c4] = *(const float4*)&pq[(size_t)d * NPIX + c4];
        *(float4*)&sk[d][c4] = *(const float4*)&pk[(size_t)d * NPIX + c4];
    }
    __syncthreads();
    {
        const int ti = (t >> 4) * 4, tj = (t & 15) * 4;
        float acc[4][4] = {};
#pragma unroll 8
        for (int d = 0; d < 32; d++) {
            float4 av = *(const float4*)&sq[d][ti];
            float4 bv = *(const float4*)&sk[d][tj];
            float a[4] = {av.x, av.y, av.z, av.w};
            float bb2[4] = {bv.x, bv.y, bv.z, bv.w};
#pragma unroll
            for (int ii = 0; ii < 4; ii++)
#pragma unroll
                for (int jj = 0; jj < 4; jj++)
                    acc[ii][jj] = fmaf(a[ii], bb2[jj], acc[ii][jj]);
        }
#pragma unroll
        for (int ii = 0; ii < 4; ii++)
#pragma unroll
            for (int jj = 0; jj < 4; jj++)
                A[ti + ii][tj + jj] = acc[ii][jj] * SCALE;
    }
    __syncthreads();
    const int wid = t >> 5, lane = t & 31;
#pragma unroll
    for (int jj = 0; jj < 8; jj++) {
        int j = wid * 8 + jj;
        float v0 = A[lane][j], v1 = A[lane + 32][j];
        float m = fmaxf(v0, v1);
#pragma unroll
        for (int s = 16; s; s >>= 1) m = fmaxf(m, __shfl_xor_sync(0xffffffffu, m, s));
        float e0 = __expf(v0 - m), e1 = __expf(v1 - m);
        float sm = e0 + e1;
#pragma unroll
        for (int s = 16; s; s >>= 1) sm += __shfl_xor_sync(0xffffffffu, sm, s);
        float inv = 1.0f / sm;
        A[lane][j] = e0 * inv;
        A[lane + 32][j] = e1 * inv;
    }
    __syncthreads();
    float* Cb = g_C + (size_t)(b * NHH + H) * 64 * NPIX + h * 64;
    for (int idx = t; idx < 64 * 64; idx += 256) {
        int jj = idx >> 6, ww = idx & 63;
        Cb[(size_t)jj * NPIX + ww] = A[jj][ww];
    }
}

// ---------------- Kernel 4 (mma.sync fp16): D[p,d] = sum_k G[p,k] V[d,k]; out = D + V
// Per CTA: (b,H), 128-p tile. 8 warps, warp w owns p rows [w*16, w*16+16), all 32 d.
// K = 4096 = 64 i-slabs x 64 j. A-frags computed in registers from R (fp32 SMEM)
// and C (fp16 SMEM, p-major). B = V slab fp16 SMEM via ldmatrix.
// SMEM: Cs [128][72] half (18432 B) | Vs [32][72] half (4608 B) | Rs [128] f32 (512 B)
// Epilogue Ds [32][132] f32 overlays Cs.
#define SM_CS 0
#define SM_VS 18432
#define SM_RS 23040
#define SM_FINAL 23552

__global__ __launch_bounds__(256) void k_final(float* __restrict__ out) {
    extern __shared__ char smc[];
    __half* Cs = (__half*)(smc + SM_CS);
    __half* Vs = (__half*)(smc + SM_VS);
    float* Rs  = (float*)(smc + SM_RS);
    float* Ds  = (float*)(smc + SM_CS);   // overlay after mainloop

    const int t = threadIdx.x, warp = t >> 5, lane = t & 31;
    const int p0 = blockIdx.x * 128;
    const int H = blockIdx.y, b = blockIdx.z;
    const int bH = b * NHH + H;
    const float* Rg = g_R + (size_t)bH * 64 * NPIX + p0;
    const float* Cg = g_C + (size_t)bH * 64 * NPIX + p0;
    const float* Vg = g_p + ((size_t)(b * OC) + H * OPH + 4 * KD) * NPIX;

    // Cs[p][j] = half(C[j][p])  — coalesced global reads along p
#pragma unroll
    for (int u = 0; u < 32; u++) {
        int e = t + u * 256;
        int j = e >> 7, p = e & 127;
        Cs[p * 72 + j] = __float2half_rn(Cg[(size_t)j * NPIX + p]);
    }

    const int prow = lane >> 2;          // 0..7
    const int qpair = lane & 3;          // 0..3
    const int pl = warp * 16 + prow;     // A rows: pl, pl+8 (local p)
    // B ldmatrix lane addressing (x2: lanes 0..15 supply rows)
    const int bl = lane & 15;
    const int brow = bl & 7;
    const int bk8 = (bl >> 3) * 8;
    // V build mapping
    const int vd = t >> 3, vj = (t & 7) * 8;

    float acc[4][4] = {};                // [ntile][frag reg]

    for (int s = 0; s < 64; s++) {
        // ---- build Rs + Vs for slab s
        if (t < 128) Rs[t] = Rg[(size_t)s * NPIX + t];
        {
            float4 v0 = *(const float4*)&Vg[(size_t)vd * NPIX + s * 64 + vj];
            float4 v1 = *(const float4*)&Vg[(size_t)vd * NPIX + s * 64 + vj + 4];
            uint4 o;
            __half2* oh = (__half2*)&o;
            oh[0] = __floats2half2_rn(v0.x, v0.y);
            oh[1] = __floats2half2_rn(v0.z, v0.w);
            oh[2] = __floats2half2_rn(v1.x, v1.y);
            oh[3] = __floats2half2_rn(v1.z, v1.w);
            *(uint4*)&Vs[vd * 72 + vj] = o;
        }
        __syncthreads();
        // ---- compute
        __half2 rlo = __half2half2(__float2half_rn(Rs[pl]));
        __half2 rhi = __half2half2(__float2half_rn(Rs[pl + 8]));
#pragma unroll
        for (int ks = 0; ks < 4; ks++) {
            int j0 = ks * 16 + qpair * 2;
            __half2 clo0 = *(__half2*)&Cs[pl * 72 + j0];
            __half2 chi0 = *(__half2*)&Cs[(pl + 8) * 72 + j0];
            __half2 clo8 = *(__half2*)&Cs[pl * 72 + j0 + 8];
            __half2 chi8 = *(__half2*)&Cs[(pl + 8) * 72 + j0 + 8];
            u32 a0 = h2u(__hmul2(rlo, clo0));
            u32 a1 = h2u(__hmul2(rhi, chi0));
            u32 a2 = h2u(__hmul2(rlo, clo8));
            u32 a3 = h2u(__hmul2(rhi, chi8));
#pragma unroll
            for (int nt = 0; nt < 4; nt++) {
                u32 baddr = smem_u32(&Vs[(nt * 8 + brow) * 72 + ks * 16 + bk8]);
                u32 b0, b1;
                asm volatile("ldmatrix.sync.aligned.m8n8.x2.shared.b16 {%0,%1}, [%2];"
                             : "=r"(b0), "=r"(b1) : "r"(baddr));
                asm volatile(
                    "mma.sync.aligned.m16n8k16.row.col.f32.f16.f16.f32 "
                    "{%0,%1,%2,%3}, {%4,%5,%6,%7}, {%8,%9}, {%0,%1,%2,%3};"
                    : "+f"(acc[nt][0]), "+f"(acc[nt][1]),
                      "+f"(acc[nt][2]), "+f"(acc[nt][3])
                    : "r"(a0), "r"(a1), "r"(a2), "r"(a3), "r"(b0), "r"(b1));
            }
        }
        __syncthreads();
    }

    // ---- epilogue: transpose through SMEM (Ds overlays Cs), add residual, store
#pragma unroll
    for (int nt = 0; nt < 4; nt++) {
        int d = nt * 8 + qpair * 2;
        Ds[d * 132 + pl]           = acc[nt][0];
        Ds[(d + 1) * 132 + pl]     = acc[nt][1];
        Ds[d * 132 + pl + 8]       = acc[nt][2];
        Ds[(d + 1) * 132 + pl + 8] = acc[nt][3];
    }
    __syncthreads();
#pragma unroll
    for (int u = 0; u < 4; u++) {
        int e = t + u * 256;
        int d = e >> 5, p4 = (e & 31) * 4;
        float4 r = *(const float4*)&Vg[(size_t)d * NPIX + p0 + p4];
        float4 v = *(const float4*)&Ds[d * 132 + p4];
        float4 o = {v.x + r.x, v.y + r.y, v.z + r.z, v.w + r.w};
        *(float4*)&out[((size_t)(b * 256) + H * 32 + d) * NPIX + p0 + p4] = o;
    }
}

extern "C" void kernel_launch(void* const* d_in, const int* in_sizes, int n_in,
                              void* d_out, int out_size) {
    const float* x = (const float*)d_in[0];
    const float* w = (const float*)d_in[1];
    if (n_in >= 2 && in_sizes[0] == OC * DIN) {
        const float* tmp = x; x = w; w = tmp;
    }
    float* out = (float*)d_out;

    k_proj<<<dim3(64, 20, BB), 256>>>(x, w);
    k_rowattn<<<dim3(64, NHH, BB), 256>>>();
    k_colattn<<<dim3(64, NHH, BB), 256>>>();
    k_final<<<dim3(32, NHH, BB), 256, SM_FINAL>>>(out);
}